// round 1
// baseline (speedup 1.0000x reference)
#include <cuda_runtime.h>
#include <math.h>

// ---------------------------------------------------------------------------
// Scratch (static device globals -- no allocation anywhere)
// ---------------------------------------------------------------------------
__device__ float g_A [128*96*72*72];        // 63,700,992 : conv1 out, later w1 out, later w4 out
__device__ float g_P1[128*96*35*35];        // 15,052,800 : pool1, later z (soft-assigned feats)
__device__ float g_F [128*1225*96];         // 15,052,800 : normalized features (B,HW,C)
__device__ float g_Km[128*1225*300];        // 47,040,000 : sinkhorn kernel matrix K
__device__ float g_u [128*1225];
__device__ float g_v [128*300];
__device__ float g_B2[128*192*17*17];       // pool2
__device__ float g_C3[128*384*17*17];       // conv w2 out
__device__ float g_D3[128*384*17*17];       // conv w3 out
__device__ float g_E [128*192*8*8];         // pool4 (flatten input to FC)
__device__ float g_fc1[128*4096];
__device__ float g_fc2[128*4096];
__device__ float g_mean[512];
__device__ float g_rstd[512];

// ---------------------------------------------------------------------------
// Generic 3x3 conv, stride 1, pad 1 (cross-correlation, NCHW / OIHW)
// Block: 128 threads, each thread 2 pixels, CO_T=16 output channels in regs.
// ---------------------------------------------------------------------------
#define CI_CHUNK 32
#define CO_T 16

__global__ void conv3x3(const float* __restrict__ in, const float* __restrict__ wt,
                        float* __restrict__ out, int Cin, int Cout, int H, int W) {
    const int HW = H * W;
    const int n   = blockIdx.z;
    const int co0 = blockIdx.y * CO_T;
    const int p0  = (blockIdx.x * blockDim.x + threadIdx.x) * 2;
    const int p1  = p0 + 1;
    const bool val0 = p0 < HW, val1 = p1 < HW;
    const int h0 = p0 / W, w0 = p0 - h0 * W;
    const int h1 = p1 / W, w1 = p1 - h1 * W;

    float acc0[CO_T], acc1[CO_T];
#pragma unroll
    for (int i = 0; i < CO_T; i++) { acc0[i] = 0.f; acc1[i] = 0.f; }

    __shared__ __align__(16) float sw[CI_CHUNK][CO_T][12];

    const float* inb = in + (size_t)n * Cin * HW;
    for (int cb = 0; cb < Cin; cb += CI_CHUNK) {
        int cc = min(CI_CHUNK, Cin - cb);
        int tot = cc * CO_T * 9;
        for (int i = threadIdx.x; i < tot; i += blockDim.x) {
            int k = i % 9; int t = i / 9; int co = t % CO_T; int ci = t / CO_T;
            sw[ci][co][k] = wt[((size_t)(co0 + co) * Cin + (cb + ci)) * 9 + k];
        }
        __syncthreads();

        for (int ci = 0; ci < cc; ci++) {
            const float* ip = inb + (size_t)(cb + ci) * HW;
            float x0[9], x1[9];
#pragma unroll
            for (int dy = 0; dy < 3; dy++) {
#pragma unroll
                for (int dx = 0; dx < 3; dx++) {
                    int hh = h0 + dy - 1, ww = w0 + dx - 1;
                    x0[dy*3+dx] = (val0 && hh >= 0 && hh < H && ww >= 0 && ww < W)
                                    ? __ldg(ip + hh * W + ww) : 0.f;
                    hh = h1 + dy - 1; ww = w1 + dx - 1;
                    x1[dy*3+dx] = (val1 && hh >= 0 && hh < H && ww >= 0 && ww < W)
                                    ? __ldg(ip + hh * W + ww) : 0.f;
                }
            }
#pragma unroll
            for (int co = 0; co < CO_T; co++) {
                const float* wp = sw[ci][co];
                float4 wa = *reinterpret_cast<const float4*>(wp);
                float4 wb = *reinterpret_cast<const float4*>(wp + 4);
                float w8 = wp[8];
                acc0[co] += x0[0]*wa.x + x0[1]*wa.y + x0[2]*wa.z + x0[3]*wa.w
                          + x0[4]*wb.x + x0[5]*wb.y + x0[6]*wb.z + x0[7]*wb.w + x0[8]*w8;
                acc1[co] += x1[0]*wa.x + x1[1]*wa.y + x1[2]*wa.z + x1[3]*wa.w
                          + x1[4]*wb.x + x1[5]*wb.y + x1[6]*wb.z + x1[7]*wb.w + x1[8]*w8;
            }
        }
        __syncthreads();
    }

#pragma unroll
    for (int co = 0; co < CO_T; co++) {
        float* op = out + ((size_t)n * Cout + co0 + co) * HW;
        if (val0) op[p0] = acc0[co];
        if (val1) op[p1] = acc1[co];
    }
}

// ---------------------------------------------------------------------------
// BatchNorm2d stats: per-channel mean + rstd over (N, H, W)
// ---------------------------------------------------------------------------
__global__ void bn2d_stats(const float* __restrict__ x, float* __restrict__ mean,
                           float* __restrict__ rstd, int N, int C, int HW) {
    int c = blockIdx.x;
    float s1 = 0.f, s2 = 0.f;
    for (int n = 0; n < N; n++) {
        const float* p = x + ((size_t)n * C + c) * HW;
        for (int j = threadIdx.x; j < HW; j += blockDim.x) {
            float v = p[j]; s1 += v; s2 += v * v;
        }
    }
    __shared__ float r1[256], r2[256];
    r1[threadIdx.x] = s1; r2[threadIdx.x] = s2;
    __syncthreads();
    for (int s = 128; s > 0; s >>= 1) {
        if (threadIdx.x < s) { r1[threadIdx.x] += r1[threadIdx.x + s];
                               r2[threadIdx.x] += r2[threadIdx.x + s]; }
        __syncthreads();
    }
    if (threadIdx.x == 0) {
        float cnt = (float)N * (float)HW;
        float m = r1[0] / cnt;
        float var = r2[0] / cnt - m * m;
        mean[c] = m;
        rstd[c] = rsqrtf(var + 1e-5f);
    }
}

// maxpool(3,2,VALID) on raw conv output, then BN + ReLU (commutes with pool)
__global__ void bnrelu_pool(const float* __restrict__ in, float* __restrict__ out,
                            const float* __restrict__ mean, const float* __restrict__ rstd,
                            int C, int H, int W, int Ho, int Wo, int total) {
    int idx = blockIdx.x * blockDim.x + threadIdx.x;
    if (idx >= total) return;
    int wo = idx % Wo; int t = idx / Wo;
    int ho = t % Ho; t /= Ho;
    int c = t % C; int n = t / C;
    const float* p = in + (((size_t)n * C + c) * H + 2 * ho) * W + 2 * wo;
    float m = -INFINITY;
#pragma unroll
    for (int r = 0; r < 3; r++)
#pragma unroll
        for (int q = 0; q < 3; q++) m = fmaxf(m, p[r * W + q]);
    float v = (m - mean[c]) * rstd[c];
    out[idx] = fmaxf(v, 0.f);
}

__global__ void bnrelu_inplace(float* __restrict__ x, const float* __restrict__ mean,
                               const float* __restrict__ rstd, int C, int HW, int total) {
    int idx = blockIdx.x * blockDim.x + threadIdx.x;
    if (idx >= total) return;
    int c = (idx / HW) % C;
    float v = (x[idx] - mean[c]) * rstd[c];
    x[idx] = fmaxf(v, 0.f);
}

// ---------------------------------------------------------------------------
// feature transpose + L2 normalize: pool1 (B,96,1225) -> feat (B,1225,96)
// ---------------------------------------------------------------------------
__global__ void feat_norm(const float* __restrict__ pool1, float* __restrict__ feat) {
    int idx = blockIdx.x * blockDim.x + threadIdx.x;
    if (idx >= 128 * 1225) return;
    int b = idx / 1225; int n = idx - b * 1225;
    const float* p = pool1 + (size_t)b * 96 * 1225 + n;
    float ss = 0.f;
#pragma unroll 8
    for (int c = 0; c < 96; c++) { float v = __ldg(p + c * 1225); ss += v * v; }
    float inv = 1.f / fmaxf(sqrtf(ss), 1e-12f);
    float* o = feat + (size_t)idx * 96;
#pragma unroll 8
    for (int c = 0; c < 96; c++) o[c] = __ldg(p + c * 1225) * inv;
}

// ---------------------------------------------------------------------------
// K[b,n,p] = exp((feat_n . proto_p - 1) * 10)   (grid: 5 x 39 x 128, block 256)
// ---------------------------------------------------------------------------
__global__ void kexp_gemm(const float* __restrict__ feat, const float* __restrict__ protos,
                          float* __restrict__ Km) {
    int b = blockIdx.z;
    int n0 = blockIdx.y * 32;
    int p0 = blockIdx.x * 64;
    __shared__ float Af[32][97];
    __shared__ float Bf[64][97];
    for (int i = threadIdx.x; i < 32 * 96; i += 256) {
        int r = i / 96, k = i % 96;
        Af[r][k] = (n0 + r < 1225) ? feat[((size_t)b * 1225 + n0 + r) * 96 + k] : 0.f;
    }
    for (int i = threadIdx.x; i < 64 * 96; i += 256) {
        int r = i / 96, k = i % 96;
        Bf[r][k] = (p0 + r < 300) ? protos[(p0 + r) * 96 + k] : 0.f;
    }
    __syncthreads();
    int tx = threadIdx.x % 64;  // p
    int ty = threadIdx.x / 64;  // 0..3
    float acc[8] = {0,0,0,0,0,0,0,0};
    for (int k = 0; k < 96; k++) {
        float bv = Bf[tx][k];
#pragma unroll
        for (int i = 0; i < 8; i++) acc[i] += Af[ty * 8 + i][k] * bv;
    }
    int p = p0 + tx;
    if (p < 300) {
#pragma unroll
        for (int i = 0; i < 8; i++) {
            int n = n0 + ty * 8 + i;
            if (n < 1225)
                Km[((size_t)b * 1225 + n) * 300 + p] = expf((acc[i] - 1.f) * 10.f);
        }
    }
}

__global__ void fill_kernel(float* p, float v, int n) {
    int i = blockIdx.x * blockDim.x + threadIdx.x;
    if (i < n) p[i] = v;
}

// v[b,p] = (1/300) / sum_n K[b,n,p] * u[b,n]      (grid 128, block 320)
__global__ void sink_v(const float* __restrict__ Km, const float* __restrict__ u,
                       float* __restrict__ v) {
    int b = blockIdx.x;
    __shared__ float su[1225];
    for (int i = threadIdx.x; i < 1225; i += blockDim.x) su[i] = u[b * 1225 + i];
    __syncthreads();
    int p = threadIdx.x;
    if (p >= 300) return;
    const float* kp = Km + (size_t)b * 1225 * 300 + p;
    float acc = 0.f;
#pragma unroll 4
    for (int n = 0; n < 1225; n++) acc += __ldg(kp + (size_t)n * 300) * su[n];
    v[b * 300 + p] = (1.f / 300.f) / acc;
}

// u[b,n] = (1/1225) / sum_p K[b,n,p] * v[b,p]     (grid 154 x 128, block 256)
__global__ void sink_u(const float* __restrict__ Km, const float* __restrict__ v,
                       float* __restrict__ u) {
    int b = blockIdx.y;
    __shared__ float sv[300];
    for (int i = threadIdx.x; i < 300; i += blockDim.x) sv[i] = v[b * 300 + i];
    __syncthreads();
    int warp = threadIdx.x / 32, lane = threadIdx.x % 32;
    int n = blockIdx.x * 8 + warp;
    if (n >= 1225) return;
    const float* kp = Km + ((size_t)b * 1225 + n) * 300;
    float acc = 0.f;
    for (int k = lane; k < 300; k += 32) acc += kp[k] * sv[k];
#pragma unroll
    for (int s = 16; s > 0; s >>= 1) acc += __shfl_xor_sync(0xffffffff, acc, s);
    if (lane == 0) u[b * 1225 + n] = (1.f / 1225.f) / acc;
}

// z[b,c,n] = 128 * u[b,n] * sum_p (K[b,n,p]*v[b,p]) * protos[p,c]
// grid (39, 128), block (96, 2)
__global__ void z_gemm(const float* __restrict__ Km, const float* __restrict__ uu,
                       const float* __restrict__ vv, const float* __restrict__ protos,
                       float* __restrict__ z) {
    int b = blockIdx.y;
    int n0 = blockIdx.x * 32;
    __shared__ float Kt[32][65];
    __shared__ float Pt[64][97];
    int tid = threadIdx.y * 96 + threadIdx.x;  // 0..191
    float acc[16];
#pragma unroll
    for (int i = 0; i < 16; i++) acc[i] = 0.f;

    for (int pc = 0; pc < 5; pc++) {
        int p0 = pc * 64;
        for (int i = tid; i < 32 * 64; i += 192) {
            int r = i / 64, j = i % 64;
            int n = n0 + r, p = p0 + j;
            Kt[r][j] = (n < 1225 && p < 300)
                         ? Km[((size_t)b * 1225 + n) * 300 + p] * __ldg(vv + b * 300 + p)
                         : 0.f;
        }
        for (int i = tid; i < 64 * 96; i += 192) {
            int r = i / 96, k = i % 96;
            Pt[r][k] = (p0 + r < 300) ? protos[(p0 + r) * 96 + k] : 0.f;
        }
        __syncthreads();
        int c = threadIdx.x;
        for (int j = 0; j < 64; j++) {
            float pv = Pt[j][c];
#pragma unroll
            for (int i = 0; i < 16; i++) acc[i] += Kt[threadIdx.y + 2 * i][j] * pv;
        }
        __syncthreads();
    }
    int c = threadIdx.x;
#pragma unroll
    for (int i = 0; i < 16; i++) {
        int n = n0 + threadIdx.y + 2 * i;
        if (n < 1225)
            z[((size_t)b * 96 + c) * 1225 + n] = 128.f * __ldg(uu + b * 1225 + n) * acc[i];
    }
}

// ---------------------------------------------------------------------------
// FC GEMM: out[M,N] = A[M,K] @ Wt[N,K]^T (+bias). M%32==0, N%64==0, K%32==0.
// grid (N/64, M/32), block 256
// ---------------------------------------------------------------------------
__global__ void fc_gemm(const float* __restrict__ A, const float* __restrict__ Wt,
                        const float* __restrict__ bias, float* __restrict__ out,
                        int M, int N, int K) {
    int n0 = blockIdx.x * 64, m0 = blockIdx.y * 32;
    __shared__ float As[32][33];
    __shared__ float Ws[64][33];
    int tx = threadIdx.x % 64, ty = threadIdx.x / 64;
    float acc[8] = {0,0,0,0,0,0,0,0};
    for (int k0 = 0; k0 < K; k0 += 32) {
        for (int i = threadIdx.x; i < 32 * 32; i += 256) {
            int r = i / 32, j = i % 32;
            As[r][j] = A[(size_t)(m0 + r) * K + k0 + j];
        }
        for (int i = threadIdx.x; i < 64 * 32; i += 256) {
            int r = i / 32, j = i % 32;
            Ws[r][j] = Wt[(size_t)(n0 + r) * K + k0 + j];
        }
        __syncthreads();
#pragma unroll
        for (int k = 0; k < 32; k++) {
            float wv = Ws[tx][k];
#pragma unroll
            for (int i = 0; i < 8; i++) acc[i] += As[ty + 4 * i][k] * wv;
        }
        __syncthreads();
    }
    float bv = bias ? bias[n0 + tx] : 0.f;
#pragma unroll
    for (int i = 0; i < 8; i++)
        out[(size_t)(m0 + ty + 4 * i) * N + n0 + tx] = acc[i] + bv;
}

// BatchNorm1d (train mode) + ReLU, in-place.  One thread per feature.
__global__ void bn1d_relu(float* __restrict__ x, int M, int N) {
    int f = blockIdx.x * blockDim.x + threadIdx.x;
    if (f >= N) return;
    float s1 = 0.f, s2 = 0.f;
    for (int r = 0; r < M; r++) {
        float v = x[(size_t)r * N + f]; s1 += v; s2 += v * v;
    }
    float m = s1 / M;
    float var = s2 / M - m * m;
    float rs = rsqrtf(var + 1e-5f);
    for (int r = 0; r < M; r++) {
        float v = x[(size_t)r * N + f];
        x[(size_t)r * N + f] = fmaxf((v - m) * rs, 0.f);
    }
}

// Row-wise L2 normalize (128 x 128).  grid 128, block 128
__global__ void l2norm(const float* __restrict__ y, float* __restrict__ out) {
    int m = blockIdx.x, t = threadIdx.x;
    float v = y[m * 128 + t];
    __shared__ float s[128];
    s[t] = v * v;
    __syncthreads();
    for (int st = 64; st > 0; st >>= 1) {
        if (t < st) s[t] += s[t + st];
        __syncthreads();
    }
    out[m * 128 + t] = v * rsqrtf(s[0]);
}

// ---------------------------------------------------------------------------
// Launch
// ---------------------------------------------------------------------------
extern "C" void kernel_launch(void* const* d_in, const int* in_sizes, int n_in,
                              void* d_out, int out_size) {
    const float* x      = (const float*)d_in[0];
    const float* sent_w = (const float*)d_in[1];
    const float* protos = (const float*)d_in[2];
    const float* w1     = (const float*)d_in[3];
    const float* w2     = (const float*)d_in[4];
    const float* w3     = (const float*)d_in[5];
    const float* w4     = (const float*)d_in[6];
    const float* w5     = (const float*)d_in[7];
    const float* w6     = (const float*)d_in[8];
    const float* w7     = (const float*)d_in[9];
    const float* b7     = (const float*)d_in[10];
    float* out = (float*)d_out;

    float *pA, *pP1, *pF, *pK, *pu, *pv, *pB2, *pC3, *pD3, *pE, *pf1, *pf2, *pm, *pr;
    cudaGetSymbolAddress((void**)&pA,  g_A);
    cudaGetSymbolAddress((void**)&pP1, g_P1);
    cudaGetSymbolAddress((void**)&pF,  g_F);
    cudaGetSymbolAddress((void**)&pK,  g_Km);
    cudaGetSymbolAddress((void**)&pu,  g_u);
    cudaGetSymbolAddress((void**)&pv,  g_v);
    cudaGetSymbolAddress((void**)&pB2, g_B2);
    cudaGetSymbolAddress((void**)&pC3, g_C3);
    cudaGetSymbolAddress((void**)&pD3, g_D3);
    cudaGetSymbolAddress((void**)&pE,  g_E);
    cudaGetSymbolAddress((void**)&pf1, g_fc1);
    cudaGetSymbolAddress((void**)&pf2, g_fc2);
    cudaGetSymbolAddress((void**)&pm,  g_mean);
    cudaGetSymbolAddress((void**)&pr,  g_rstd);

    // sentinel block: conv(2->96, 72x72) + BN + ReLU + pool -> (96,35,35)
    conv3x3<<<dim3(21, 6, 128), 128>>>(x, sent_w, pA, 2, 96, 72, 72);
    bn2d_stats<<<96, 256>>>(pA, pm, pr, 128, 96, 72 * 72);
    {
        int total = 128 * 96 * 35 * 35;
        bnrelu_pool<<<(total + 255) / 256, 256>>>(pA, pP1, pm, pr, 96, 72, 72, 35, 35, total);
    }

    // prototypes: normalize features, K = exp((S-1)*10)
    feat_norm<<<(128 * 1225 + 255) / 256, 256>>>(pP1, pF);
    kexp_gemm<<<dim3(5, 39, 128), 256>>>(pF, protos, pK);

    // sinkhorn (10 iterations)
    fill_kernel<<<(128 * 1225 + 255) / 256, 256>>>(pu, 1.f, 128 * 1225);
    for (int it = 0; it < 10; it++) {
        sink_v<<<128, 320>>>(pK, pu, pv);
        sink_u<<<dim3(154, 128), 256>>>(pK, pv, pu);
    }
    // z = 128 * (u . K . v) @ protos  ->  NCHW (96,35,35), overwrite pool1 buffer
    z_gemm<<<dim3(39, 128), dim3(96, 2)>>>(pK, pu, pv, protos, pP1);

    // encoder block 1: conv 96->192 (35x35) + BN + ReLU + pool -> (192,17,17)
    conv3x3<<<dim3(5, 12, 128), 128>>>(pP1, w1, pA, 96, 192, 35, 35);
    bn2d_stats<<<192, 256>>>(pA, pm, pr, 128, 192, 35 * 35);
    {
        int total = 128 * 192 * 17 * 17;
        bnrelu_pool<<<(total + 255) / 256, 256>>>(pA, pB2, pm, pr, 192, 35, 35, 17, 17, total);
    }

    // block 2: conv 192->384 (17x17) + BN + ReLU
    conv3x3<<<dim3(2, 24, 128), 128>>>(pB2, w2, pC3, 192, 384, 17, 17);
    bn2d_stats<<<384, 256>>>(pC3, pm, pr, 128, 384, 289);
    {
        int total = 128 * 384 * 289;
        bnrelu_inplace<<<(total + 255) / 256, 256>>>(pC3, pm, pr, 384, 289, total);
    }

    // block 3: conv 384->384 (17x17) + BN + ReLU
    conv3x3<<<dim3(2, 24, 128), 128>>>(pC3, w3, pD3, 384, 384, 17, 17);
    bn2d_stats<<<384, 256>>>(pD3, pm, pr, 128, 384, 289);
    {
        int total = 128 * 384 * 289;
        bnrelu_inplace<<<(total + 255) / 256, 256>>>(pD3, pm, pr, 384, 289, total);
    }

    // block 4: conv 384->192 (17x17) + BN + ReLU + pool -> (192,8,8)
    conv3x3<<<dim3(2, 12, 128), 128>>>(pD3, w4, pA, 384, 192, 17, 17);
    bn2d_stats<<<192, 256>>>(pA, pm, pr, 128, 192, 289);
    {
        int total = 128 * 192 * 8 * 8;
        bnrelu_pool<<<(total + 255) / 256, 256>>>(pA, pE, pm, pr, 192, 17, 17, 8, 8, total);
    }

    // FC head
    fc_gemm<<<dim3(64, 4), 256>>>(pE, w5, nullptr, pf1, 128, 4096, 12288);
    bn1d_relu<<<16, 256>>>(pf1, 128, 4096);
    fc_gemm<<<dim3(64, 4), 256>>>(pf1, w6, nullptr, pf2, 128, 4096, 4096);
    bn1d_relu<<<16, 256>>>(pf2, 128, 4096);
    fc_gemm<<<dim3(2, 4), 256>>>(pf2, w7, b7, pf1, 128, 128, 4096);
    l2norm<<<128, 128>>>(pf1, out);
}

// round 3
// speedup vs baseline: 1.2554x; 1.2554x over previous
#include <cuda_runtime.h>
#include <math.h>

// ---------------------------------------------------------------------------
// Scratch (static device globals -- no allocation anywhere)
// ---------------------------------------------------------------------------
__device__ float g_A [128*96*72*72];        // conv1 out, later w1 out, later w4 out
__device__ float g_P1[128*96*35*35];        // pool1, later z (soft-assigned feats)
__device__ float g_F [128*1225*96];         // normalized features (B,HW,C)
__device__ float g_Km[128*1225*300];        // sinkhorn kernel matrix K
__device__ float g_u [128*1225];
__device__ float g_v [128*300];
__device__ float g_B2[128*192*17*17];       // pool2
__device__ float g_C3[128*384*17*17];       // conv w2 out
__device__ float g_D3[128*384*17*17];       // conv w3 out
__device__ float g_E [128*192*8*8];         // pool4 (flatten input to FC)
__device__ float g_fc1[128*4096];
__device__ float g_fc2[128*4096];
__device__ float g_mean[512];
__device__ float g_rstd[512];
__device__ float g_part[512*16*2];          // BN partial sums

// ---------------------------------------------------------------------------
// Generic 3x3 conv, stride 1, pad 1 (cross-correlation, NCHW / OIHW)
// Each thread: 2 pixels, CO_T=16 output channels in regs.
// ---------------------------------------------------------------------------
#define CI_CHUNK 32
#define CO_T 16

__global__ void conv3x3(const float* __restrict__ in, const float* __restrict__ wt,
                        float* __restrict__ out, int Cin, int Cout, int H, int W) {
    const int HW = H * W;
    const int n   = blockIdx.z;
    const int co0 = blockIdx.y * CO_T;
    const int p0  = (blockIdx.x * blockDim.x + threadIdx.x) * 2;
    const int p1  = p0 + 1;
    const bool val0 = p0 < HW, val1 = p1 < HW;
    const int h0 = p0 / W, w0 = p0 - h0 * W;
    const int h1 = p1 / W, w1 = p1 - h1 * W;

    float acc0[CO_T], acc1[CO_T];
#pragma unroll
    for (int i = 0; i < CO_T; i++) { acc0[i] = 0.f; acc1[i] = 0.f; }

    __shared__ __align__(16) float sw[CI_CHUNK][CO_T][12];

    const float* inb = in + (size_t)n * Cin * HW;
    for (int cb = 0; cb < Cin; cb += CI_CHUNK) {
        int cc = min(CI_CHUNK, Cin - cb);
        int tot = cc * CO_T * 9;
        for (int i = threadIdx.x; i < tot; i += blockDim.x) {
            int k = i % 9; int t = i / 9; int co = t % CO_T; int ci = t / CO_T;
            sw[ci][co][k] = wt[((size_t)(co0 + co) * Cin + (cb + ci)) * 9 + k];
        }
        __syncthreads();

        for (int ci = 0; ci < cc; ci++) {
            const float* ip = inb + (size_t)(cb + ci) * HW;
            float x0[9], x1[9];
#pragma unroll
            for (int dy = 0; dy < 3; dy++) {
#pragma unroll
                for (int dx = 0; dx < 3; dx++) {
                    int hh = h0 + dy - 1, ww = w0 + dx - 1;
                    x0[dy*3+dx] = (val0 && hh >= 0 && hh < H && ww >= 0 && ww < W)
                                    ? __ldg(ip + hh * W + ww) : 0.f;
                    hh = h1 + dy - 1; ww = w1 + dx - 1;
                    x1[dy*3+dx] = (val1 && hh >= 0 && hh < H && ww >= 0 && ww < W)
                                    ? __ldg(ip + hh * W + ww) : 0.f;
                }
            }
#pragma unroll
            for (int co = 0; co < CO_T; co++) {
                const float* wp = sw[ci][co];
                float4 wa = *reinterpret_cast<const float4*>(wp);
                float4 wb = *reinterpret_cast<const float4*>(wp + 4);
                float w8 = wp[8];
                acc0[co] += x0[0]*wa.x + x0[1]*wa.y + x0[2]*wa.z + x0[3]*wa.w
                          + x0[4]*wb.x + x0[5]*wb.y + x0[6]*wb.z + x0[7]*wb.w + x0[8]*w8;
                acc1[co] += x1[0]*wa.x + x1[1]*wa.y + x1[2]*wa.z + x1[3]*wa.w
                          + x1[4]*wb.x + x1[5]*wb.y + x1[6]*wb.z + x1[7]*wb.w + x1[8]*w8;
            }
        }
        __syncthreads();
    }

#pragma unroll
    for (int co = 0; co < CO_T; co++) {
        float* op = out + ((size_t)n * Cout + co0 + co) * HW;
        if (val0) op[p0] = acc0[co];
        if (val1) op[p1] = acc1[co];
    }
}

// ---------------------------------------------------------------------------
// BatchNorm2d stats, two-stage.
// Stage 1: grid (C, SL) -- each block reduces a batch slice of channel c.
// ---------------------------------------------------------------------------
#define BN_SL 16
__global__ void bn2d_part(const float* __restrict__ x, float* __restrict__ part,
                          int N, int C, int HW) {
    int c = blockIdx.x, sl = blockIdx.y;
    int nper = N / BN_SL;
    float s1 = 0.f, s2 = 0.f;
    for (int n = sl * nper; n < (sl + 1) * nper; n++) {
        const float* p = x + ((size_t)n * C + c) * HW;
        for (int j = threadIdx.x; j < HW; j += blockDim.x) {
            float v = p[j]; s1 += v; s2 += v * v;
        }
    }
    __shared__ float r1[256], r2[256];
    r1[threadIdx.x] = s1; r2[threadIdx.x] = s2;
    __syncthreads();
    for (int s = 128; s > 0; s >>= 1) {
        if (threadIdx.x < s) { r1[threadIdx.x] += r1[threadIdx.x + s];
                               r2[threadIdx.x] += r2[threadIdx.x + s]; }
        __syncthreads();
    }
    if (threadIdx.x == 0) {
        part[(c * BN_SL + sl) * 2 + 0] = r1[0];
        part[(c * BN_SL + sl) * 2 + 1] = r2[0];
    }
}

__global__ void bn2d_fin(const float* __restrict__ part, float* __restrict__ mean,
                         float* __restrict__ rstd, int C, float count) {
    int c = blockIdx.x * blockDim.x + threadIdx.x;
    if (c >= C) return;
    float s1 = 0.f, s2 = 0.f;
#pragma unroll
    for (int j = 0; j < BN_SL; j++) {
        s1 += part[(c * BN_SL + j) * 2 + 0];
        s2 += part[(c * BN_SL + j) * 2 + 1];
    }
    float m = s1 / count;
    float var = s2 / count - m * m;
    mean[c] = m;
    rstd[c] = rsqrtf(var + 1e-5f);
}

// maxpool(3,2,VALID) on raw conv output, then BN + ReLU (commutes with pool)
__global__ void bnrelu_pool(const float* __restrict__ in, float* __restrict__ out,
                            const float* __restrict__ mean, const float* __restrict__ rstd,
                            int C, int H, int W, int Ho, int Wo, int total) {
    int idx = blockIdx.x * blockDim.x + threadIdx.x;
    if (idx >= total) return;
    int wo = idx % Wo; int t = idx / Wo;
    int ho = t % Ho; t /= Ho;
    int c = t % C; int n = t / C;
    const float* p = in + (((size_t)n * C + c) * H + 2 * ho) * W + 2 * wo;
    float m = -INFINITY;
#pragma unroll
    for (int r = 0; r < 3; r++)
#pragma unroll
        for (int q = 0; q < 3; q++) m = fmaxf(m, p[r * W + q]);
    float v = (m - mean[c]) * rstd[c];
    out[idx] = fmaxf(v, 0.f);
}

__global__ void bnrelu_inplace(float* __restrict__ x, const float* __restrict__ mean,
                               const float* __restrict__ rstd, int C, int HW, int total) {
    int idx = blockIdx.x * blockDim.x + threadIdx.x;
    if (idx >= total) return;
    int c = (idx / HW) % C;
    float v = (x[idx] - mean[c]) * rstd[c];
    x[idx] = fmaxf(v, 0.f);
}

// ---------------------------------------------------------------------------
// feature transpose + L2 normalize: pool1 (B,96,1225) -> feat (B,1225,96)
// ---------------------------------------------------------------------------
__global__ void feat_norm(const float* __restrict__ pool1, float* __restrict__ feat) {
    int idx = blockIdx.x * blockDim.x + threadIdx.x;
    if (idx >= 128 * 1225) return;
    int b = idx / 1225; int n = idx - b * 1225;
    const float* p = pool1 + (size_t)b * 96 * 1225 + n;
    float ss = 0.f;
#pragma unroll 8
    for (int c = 0; c < 96; c++) { float v = __ldg(p + c * 1225); ss += v * v; }
    float inv = 1.f / fmaxf(sqrtf(ss), 1e-12f);
    float* o = feat + (size_t)idx * 96;
#pragma unroll 8
    for (int c = 0; c < 96; c++) o[c] = __ldg(p + c * 1225) * inv;
}

// ---------------------------------------------------------------------------
// K[b,n,p] = exp((feat_n . proto_p - 1) * 10)
// ---------------------------------------------------------------------------
__global__ void kexp_gemm(const float* __restrict__ feat, const float* __restrict__ protos,
                          float* __restrict__ Km) {
    int b = blockIdx.z;
    int n0 = blockIdx.y * 32;
    int p0 = blockIdx.x * 64;
    __shared__ float Af[32][97];
    __shared__ float Bf[64][97];
    for (int i = threadIdx.x; i < 32 * 96; i += 256) {
        int r = i / 96, k = i % 96;
        Af[r][k] = (n0 + r < 1225) ? feat[((size_t)b * 1225 + n0 + r) * 96 + k] : 0.f;
    }
    for (int i = threadIdx.x; i < 64 * 96; i += 256) {
        int r = i / 96, k = i % 96;
        Bf[r][k] = (p0 + r < 300) ? protos[(p0 + r) * 96 + k] : 0.f;
    }
    __syncthreads();
    int tx = threadIdx.x % 64;
    int ty = threadIdx.x / 64;
    float acc[8] = {0,0,0,0,0,0,0,0};
    for (int k = 0; k < 96; k++) {
        float bv = Bf[tx][k];
#pragma unroll
        for (int i = 0; i < 8; i++) acc[i] += Af[ty * 8 + i][k] * bv;
    }
    int p = p0 + tx;
    if (p < 300) {
#pragma unroll
        for (int i = 0; i < 8; i++) {
            int n = n0 + ty * 8 + i;
            if (n < 1225)
                Km[((size_t)b * 1225 + n) * 300 + p] = expf((acc[i] - 1.f) * 10.f);
        }
    }
}

__global__ void fill_kernel(float* p, float v, int n) {
    int i = blockIdx.x * blockDim.x + threadIdx.x;
    if (i < n) p[i] = v;
}

// v[b,p] = (1/300) / sum_n K[b,n,p] * u[b,n]
__global__ void sink_v(const float* __restrict__ Km, const float* __restrict__ u,
                       float* __restrict__ v) {
    int b = blockIdx.x;
    __shared__ float su[1225];
    for (int i = threadIdx.x; i < 1225; i += blockDim.x) su[i] = u[b * 1225 + i];
    __syncthreads();
    int p = threadIdx.x;
    if (p >= 300) return;
    const float* kp = Km + (size_t)b * 1225 * 300 + p;
    float acc = 0.f;
#pragma unroll 4
    for (int n = 0; n < 1225; n++) acc += __ldg(kp + (size_t)n * 300) * su[n];
    v[b * 300 + p] = (1.f / 300.f) / acc;
}

// u[b,n] = (1/1225) / sum_p K[b,n,p] * v[b,p]
__global__ void sink_u(const float* __restrict__ Km, const float* __restrict__ v,
                       float* __restrict__ u) {
    int b = blockIdx.y;
    __shared__ float sv[300];
    for (int i = threadIdx.x; i < 300; i += blockDim.x) sv[i] = v[b * 300 + i];
    __syncthreads();
    int warp = threadIdx.x / 32, lane = threadIdx.x % 32;
    int n = blockIdx.x * 8 + warp;
    if (n >= 1225) return;
    const float* kp = Km + ((size_t)b * 1225 + n) * 300;
    float acc = 0.f;
    for (int k = lane; k < 300; k += 32) acc += kp[k] * sv[k];
#pragma unroll
    for (int s = 16; s > 0; s >>= 1) acc += __shfl_xor_sync(0xffffffff, acc, s);
    if (lane == 0) u[b * 1225 + n] = (1.f / 1225.f) / acc;
}

// z[b,c,n] = 128 * u[b,n] * sum_p (K[b,n,p]*v[b,p]) * protos[p,c]
__global__ void z_gemm(const float* __restrict__ Km, const float* __restrict__ uu,
                       const float* __restrict__ vv, const float* __restrict__ protos,
                       float* __restrict__ z) {
    int b = blockIdx.y;
    int n0 = blockIdx.x * 32;
    __shared__ float Kt[32][65];
    __shared__ float Pt[64][97];
    int tid = threadIdx.y * 96 + threadIdx.x;
    float acc[16];
#pragma unroll
    for (int i = 0; i < 16; i++) acc[i] = 0.f;

    for (int pc = 0; pc < 5; pc++) {
        int p0 = pc * 64;
        for (int i = tid; i < 32 * 64; i += 192) {
            int r = i / 64, j = i % 64;
            int n = n0 + r, p = p0 + j;
            Kt[r][j] = (n < 1225 && p < 300)
                         ? Km[((size_t)b * 1225 + n) * 300 + p] * __ldg(vv + b * 300 + p)
                         : 0.f;
        }
        for (int i = tid; i < 64 * 96; i += 192) {
            int r = i / 96, k = i % 96;
            Pt[r][k] = (p0 + r < 300) ? protos[(p0 + r) * 96 + k] : 0.f;
        }
        __syncthreads();
        int c = threadIdx.x;
        for (int j = 0; j < 64; j++) {
            float pv = Pt[j][c];
#pragma unroll
            for (int i = 0; i < 16; i++) acc[i] += Kt[threadIdx.y + 2 * i][j] * pv;
        }
        __syncthreads();
    }
    int c = threadIdx.x;
#pragma unroll
    for (int i = 0; i < 16; i++) {
        int n = n0 + threadIdx.y + 2 * i;
        if (n < 1225)
            z[((size_t)b * 96 + c) * 1225 + n] = 128.f * __ldg(uu + b * 1225 + n) * acc[i];
    }
}

// ---------------------------------------------------------------------------
// FC GEMM: out[M,N] = A[M,K] @ Wt[N,K]^T (+bias)
// Tile: 32 rows x 128 cols, block 256 = (32 tx) x (8 ty), 4x4 per thread.
// Requires M%32==0, N%128==0, K%32==0.
// ---------------------------------------------------------------------------
__global__ void fc_gemm(const float* __restrict__ A, const float* __restrict__ Wt,
                        const float* __restrict__ bias, float* __restrict__ out,
                        int M, int N, int K) {
    int n0 = blockIdx.x * 128, m0 = blockIdx.y * 32;
    __shared__ float As[32][33];
    __shared__ float Ws[128][33];
    int tx = threadIdx.x % 32, ty = threadIdx.x / 32;  // ty 0..7
    float acc[4][4];
#pragma unroll
    for (int i = 0; i < 4; i++)
#pragma unroll
        for (int j = 0; j < 4; j++) acc[i][j] = 0.f;

    for (int k0 = 0; k0 < K; k0 += 32) {
        for (int i = threadIdx.x; i < 32 * 32; i += 256) {
            int r = i / 32, j = i % 32;
            As[r][j] = A[(size_t)(m0 + r) * K + k0 + j];
        }
        for (int i = threadIdx.x; i < 128 * 32; i += 256) {
            int r = i / 32, j = i % 32;
            Ws[r][j] = Wt[(size_t)(n0 + r) * K + k0 + j];
        }
        __syncthreads();
#pragma unroll
        for (int k = 0; k < 32; k++) {
            float a[4], w[4];
#pragma unroll
            for (int i = 0; i < 4; i++) a[i] = As[ty + 8 * i][k];
#pragma unroll
            for (int j = 0; j < 4; j++) w[j] = Ws[tx + 32 * j][k];
#pragma unroll
            for (int i = 0; i < 4; i++)
#pragma unroll
                for (int j = 0; j < 4; j++) acc[i][j] += a[i] * w[j];
        }
        __syncthreads();
    }
#pragma unroll
    for (int j = 0; j < 4; j++) {
        float bv = bias ? bias[n0 + tx + 32 * j] : 0.f;
#pragma unroll
        for (int i = 0; i < 4; i++)
            out[(size_t)(m0 + ty + 8 * i) * N + n0 + tx + 32 * j] = acc[i][j] + bv;
    }
}

// BatchNorm1d (train mode) + ReLU, in-place.  One thread per feature.
__global__ void bn1d_relu(float* __restrict__ x, int M, int N) {
    int f = blockIdx.x * blockDim.x + threadIdx.x;
    if (f >= N) return;
    float s1 = 0.f, s2 = 0.f;
    for (int r = 0; r < M; r++) {
        float v = x[(size_t)r * N + f]; s1 += v; s2 += v * v;
    }
    float m = s1 / M;
    float var = s2 / M - m * m;
    float rs = rsqrtf(var + 1e-5f);
    for (int r = 0; r < M; r++) {
        float v = x[(size_t)r * N + f];
        x[(size_t)r * N + f] = fmaxf((v - m) * rs, 0.f);
    }
}

// Row-wise L2 normalize (128 x 128)
__global__ void l2norm(const float* __restrict__ y, float* __restrict__ out) {
    int m = blockIdx.x, t = threadIdx.x;
    float v = y[m * 128 + t];
    __shared__ float s[128];
    s[t] = v * v;
    __syncthreads();
    for (int st = 64; st > 0; st >>= 1) {
        if (t < st) s[t] += s[t + st];
        __syncthreads();
    }
    out[m * 128 + t] = v * rsqrtf(s[0]);
}

// ---------------------------------------------------------------------------
// Launch
// ---------------------------------------------------------------------------
extern "C" void kernel_launch(void* const* d_in, const int* in_sizes, int n_in,
                              void* d_out, int out_size) {
    const float* x      = (const float*)d_in[0];
    const float* sent_w = (const float*)d_in[1];
    const float* protos = (const float*)d_in[2];
    const float* w1     = (const float*)d_in[3];
    const float* w2     = (const float*)d_in[4];
    const float* w3     = (const float*)d_in[5];
    const float* w4     = (const float*)d_in[6];
    const float* w5     = (const float*)d_in[7];
    const float* w6     = (const float*)d_in[8];
    const float* w7     = (const float*)d_in[9];
    const float* b7     = (const float*)d_in[10];
    float* out = (float*)d_out;

    float *pA, *pP1, *pF, *pK, *pu, *pv, *pB2, *pC3, *pD3, *pE, *pf1, *pf2, *pm, *pr, *pp;
    cudaGetSymbolAddress((void**)&pA,  g_A);
    cudaGetSymbolAddress((void**)&pP1, g_P1);
    cudaGetSymbolAddress((void**)&pF,  g_F);
    cudaGetSymbolAddress((void**)&pK,  g_Km);
    cudaGetSymbolAddress((void**)&pu,  g_u);
    cudaGetSymbolAddress((void**)&pv,  g_v);
    cudaGetSymbolAddress((void**)&pB2, g_B2);
    cudaGetSymbolAddress((void**)&pC3, g_C3);
    cudaGetSymbolAddress((void**)&pD3, g_D3);
    cudaGetSymbolAddress((void**)&pE,  g_E);
    cudaGetSymbolAddress((void**)&pf1, g_fc1);
    cudaGetSymbolAddress((void**)&pf2, g_fc2);
    cudaGetSymbolAddress((void**)&pm,  g_mean);
    cudaGetSymbolAddress((void**)&pr,  g_rstd);
    cudaGetSymbolAddress((void**)&pp,  g_part);

    // sentinel block: conv(2->96, 72x72) + BN + ReLU + pool -> (96,35,35)
    conv3x3<<<dim3(21, 6, 128), 128>>>(x, sent_w, pA, 2, 96, 72, 72);
    bn2d_part<<<dim3(96, BN_SL), 256>>>(pA, pp, 128, 96, 72 * 72);
    bn2d_fin<<<1, 512>>>(pp, pm, pr, 96, 128.f * 5184.f);
    {
        int total = 128 * 96 * 35 * 35;
        bnrelu_pool<<<(total + 255) / 256, 256>>>(pA, pP1, pm, pr, 96, 72, 72, 35, 35, total);
    }

    // prototypes: normalize features, K = exp((S-1)*10)
    feat_norm<<<(128 * 1225 + 255) / 256, 256>>>(pP1, pF);
    kexp_gemm<<<dim3(5, 39, 128), 256>>>(pF, protos, pK);

    // sinkhorn (10 iterations)
    fill_kernel<<<(128 * 1225 + 255) / 256, 256>>>(pu, 1.f, 128 * 1225);
    for (int it = 0; it < 10; it++) {
        sink_v<<<128, 320>>>(pK, pu, pv);
        sink_u<<<dim3(154, 128), 256>>>(pK, pv, pu);
    }
    z_gemm<<<dim3(39, 128), dim3(96, 2)>>>(pK, pu, pv, protos, pP1);

    // encoder block 1: conv 96->192 (35x35) + BN + ReLU + pool -> (192,17,17)
    conv3x3<<<dim3(5, 12, 128), 128>>>(pP1, w1, pA, 96, 192, 35, 35);
    bn2d_part<<<dim3(192, BN_SL), 256>>>(pA, pp, 128, 192, 1225);
    bn2d_fin<<<1, 512>>>(pp, pm, pr, 192, 128.f * 1225.f);
    {
        int total = 128 * 192 * 17 * 17;
        bnrelu_pool<<<(total + 255) / 256, 256>>>(pA, pB2, pm, pr, 192, 35, 35, 17, 17, total);
    }

    // block 2: conv 192->384 (17x17) + BN + ReLU   (289 px -> 160 thr x 2 px)
    conv3x3<<<dim3(1, 24, 128), 160>>>(pB2, w2, pC3, 192, 384, 17, 17);
    bn2d_part<<<dim3(384, BN_SL), 256>>>(pC3, pp, 128, 384, 289);
    bn2d_fin<<<1, 512>>>(pp, pm, pr, 384, 128.f * 289.f);
    {
        int total = 128 * 384 * 289;
        bnrelu_inplace<<<(total + 255) / 256, 256>>>(pC3, pm, pr, 384, 289, total);
    }

    // block 3: conv 384->384 (17x17) + BN + ReLU
    conv3x3<<<dim3(1, 24, 128), 160>>>(pC3, w3, pD3, 384, 384, 17, 17);
    bn2d_part<<<dim3(384, BN_SL), 256>>>(pD3, pp, 128, 384, 289);
    bn2d_fin<<<1, 512>>>(pp, pm, pr, 384, 128.f * 289.f);
    {
        int total = 128 * 384 * 289;
        bnrelu_inplace<<<(total + 255) / 256, 256>>>(pD3, pm, pr, 384, 289, total);
    }

    // block 4: conv 384->192 (17x17) + BN + ReLU + pool -> (192,8,8)
    conv3x3<<<dim3(1, 12, 128), 160>>>(pD3, w4, pA, 384, 192, 17, 17);
    bn2d_part<<<dim3(192, BN_SL), 256>>>(pA, pp, 128, 192, 289);
    bn2d_fin<<<1, 512>>>(pp, pm, pr, 192, 128.f * 289.f);
    {
        int total = 128 * 192 * 8 * 8;
        bnrelu_pool<<<(total + 255) / 256, 256>>>(pA, pE, pm, pr, 192, 17, 17, 8, 8, total);
    }

    // FC head
    fc_gemm<<<dim3(32, 4), 256>>>(pE, w5, nullptr, pf1, 128, 4096, 12288);
    bn1d_relu<<<16, 256>>>(pf1, 128, 4096);
    fc_gemm<<<dim3(32, 4), 256>>>(pf1, w6, nullptr, pf2, 128, 4096, 4096);
    bn1d_relu<<<16, 256>>>(pf2, 128, 4096);
    fc_gemm<<<dim3(1, 4), 256>>>(pf2, w7, b7, pf1, 128, 128, 4096);
    l2norm<<<128, 128>>>(pf1, out);
}

// round 4
// speedup vs baseline: 1.3370x; 1.0650x over previous
#include <cuda_runtime.h>
#include <math.h>

// ---------------------------------------------------------------------------
// Scratch (static device globals -- no allocation anywhere)
// ---------------------------------------------------------------------------
__device__ float g_A [128*96*72*72];        // conv1 out, later w1 out, later w4 out
__device__ float g_P1[128*96*35*35];        // pool1, later z (soft-assigned feats)
__device__ float g_F [128*1225*96];         // normalized features (B,HW,C)
__device__ float g_Km[128*1225*300];        // sinkhorn kernel matrix K
__device__ float g_u [128*1225];
__device__ float g_v [128*300];
__device__ float g_B2[128*192*17*17];       // pool2
__device__ float g_C3[128*384*17*17];       // conv w2 out
__device__ float g_D3[128*384*17*17];       // conv w3 out
__device__ float g_E [128*192*8*8];         // pool4 (flatten input to FC)
__device__ float g_fc1[128*4096];
__device__ float g_fc2[128*4096];
__device__ float g_mean[512];
__device__ float g_rstd[512];
__device__ float g_part[512*16*2];          // BN partial sums

// ---------------------------------------------------------------------------
// Generic 3x3 conv, stride 1, pad 1 (cross-correlation, NCHW / OIHW)
// Each thread: 2 pixels packed into f32x2 lanes, CO_T=16 output channels.
// Inner product uses fma.rn.f32x2 (FFMA2): 2 fp32 FMAs per issue slot.
// Weights staged in shared memory PRE-DUPLICATED as float2{w,w} so the
// multiplier operand is a direct LDS, no per-FMA packing.
// ---------------------------------------------------------------------------
#define CI_CHUNK 32
#define CO_T 16

__global__ void conv3x3(const float* __restrict__ in, const float* __restrict__ wt,
                        float* __restrict__ out, int Cin, int Cout, int H, int W) {
    const int HW = H * W;
    const int n   = blockIdx.z;
    const int co0 = blockIdx.y * CO_T;
    const int p0  = (blockIdx.x * blockDim.x + threadIdx.x) * 2;
    const int p1  = p0 + 1;
    const bool val0 = p0 < HW, val1 = p1 < HW;
    const int h0 = p0 / W, w0 = p0 - h0 * W;
    const int h1 = p1 / W, w1 = p1 - h1 * W;

    unsigned long long acc[CO_T];
#pragma unroll
    for (int i = 0; i < CO_T; i++) acc[i] = 0ull;

    // [ci][co][k] duplicated weight pairs; k padded 9->10 (80B row, 16B aligned)
    __shared__ __align__(16) float2 sw[CI_CHUNK][CO_T][10];

    const float* inb = in + (size_t)n * Cin * HW;
    for (int cb = 0; cb < Cin; cb += CI_CHUNK) {
        int cc = min(CI_CHUNK, Cin - cb);
        int tot = cc * CO_T * 9;
        for (int i = threadIdx.x; i < tot; i += blockDim.x) {
            int k = i % 9; int t = i / 9; int co = t % CO_T; int ci = t / CO_T;
            float wv = wt[((size_t)(co0 + co) * Cin + (cb + ci)) * 9 + k];
            sw[ci][co][k] = make_float2(wv, wv);
        }
        __syncthreads();

        for (int ci = 0; ci < cc; ci++) {
            const float* ip = inb + (size_t)(cb + ci) * HW;
            unsigned long long x01[9];
#pragma unroll
            for (int dy = 0; dy < 3; dy++) {
#pragma unroll
                for (int dx = 0; dx < 3; dx++) {
                    int hh = h0 + dy - 1, ww = w0 + dx - 1;
                    float a = (val0 && hh >= 0 && hh < H && ww >= 0 && ww < W)
                                ? __ldg(ip + hh * W + ww) : 0.f;
                    hh = h1 + dy - 1; ww = w1 + dx - 1;
                    float b = (val1 && hh >= 0 && hh < H && ww >= 0 && ww < W)
                                ? __ldg(ip + hh * W + ww) : 0.f;
                    asm("mov.b64 %0, {%1, %2};"
                        : "=l"(x01[dy * 3 + dx]) : "f"(a), "f"(b));
                }
            }
#pragma unroll
            for (int co = 0; co < CO_T; co++) {
                const unsigned long long* wp =
                    reinterpret_cast<const unsigned long long*>(sw[ci][co]);
#pragma unroll
                for (int k = 0; k < 9; k++) {
                    unsigned long long wk = wp[k];
                    asm("fma.rn.f32x2 %0, %1, %2, %3;"
                        : "=l"(acc[co]) : "l"(x01[k]), "l"(wk), "l"(acc[co]));
                }
            }
        }
        __syncthreads();
    }

#pragma unroll
    for (int co = 0; co < CO_T; co++) {
        float lo, hi;
        asm("mov.b64 {%0, %1}, %2;" : "=f"(lo), "=f"(hi) : "l"(acc[co]));
        float* op = out + ((size_t)n * Cout + co0 + co) * HW;
        if (val0) op[p0] = lo;
        if (val1) op[p1] = hi;
    }
}

// ---------------------------------------------------------------------------
// BatchNorm2d stats, two-stage.
// ---------------------------------------------------------------------------
#define BN_SL 16
__global__ void bn2d_part(const float* __restrict__ x, float* __restrict__ part,
                          int N, int C, int HW) {
    int c = blockIdx.x, sl = blockIdx.y;
    int nper = N / BN_SL;
    float s1 = 0.f, s2 = 0.f;
    for (int n = sl * nper; n < (sl + 1) * nper; n++) {
        const float* p = x + ((size_t)n * C + c) * HW;
        for (int j = threadIdx.x; j < HW; j += blockDim.x) {
            float v = p[j]; s1 += v; s2 += v * v;
        }
    }
    __shared__ float r1[256], r2[256];
    r1[threadIdx.x] = s1; r2[threadIdx.x] = s2;
    __syncthreads();
    for (int s = 128; s > 0; s >>= 1) {
        if (threadIdx.x < s) { r1[threadIdx.x] += r1[threadIdx.x + s];
                               r2[threadIdx.x] += r2[threadIdx.x + s]; }
        __syncthreads();
    }
    if (threadIdx.x == 0) {
        part[(c * BN_SL + sl) * 2 + 0] = r1[0];
        part[(c * BN_SL + sl) * 2 + 1] = r2[0];
    }
}

__global__ void bn2d_fin(const float* __restrict__ part, float* __restrict__ mean,
                         float* __restrict__ rstd, int C, float count) {
    int c = blockIdx.x * blockDim.x + threadIdx.x;
    if (c >= C) return;
    float s1 = 0.f, s2 = 0.f;
#pragma unroll
    for (int j = 0; j < BN_SL; j++) {
        s1 += part[(c * BN_SL + j) * 2 + 0];
        s2 += part[(c * BN_SL + j) * 2 + 1];
    }
    float m = s1 / count;
    float var = s2 / count - m * m;
    mean[c] = m;
    rstd[c] = rsqrtf(var + 1e-5f);
}

// maxpool(3,2,VALID) on raw conv output, then BN + ReLU (commutes with pool)
__global__ void bnrelu_pool(const float* __restrict__ in, float* __restrict__ out,
                            const float* __restrict__ mean, const float* __restrict__ rstd,
                            int C, int H, int W, int Ho, int Wo, int total) {
    int idx = blockIdx.x * blockDim.x + threadIdx.x;
    if (idx >= total) return;
    int wo = idx % Wo; int t = idx / Wo;
    int ho = t % Ho; t /= Ho;
    int c = t % C; int n = t / C;
    const float* p = in + (((size_t)n * C + c) * H + 2 * ho) * W + 2 * wo;
    float m = -INFINITY;
#pragma unroll
    for (int r = 0; r < 3; r++)
#pragma unroll
        for (int q = 0; q < 3; q++) m = fmaxf(m, p[r * W + q]);
    float v = (m - mean[c]) * rstd[c];
    out[idx] = fmaxf(v, 0.f);
}

__global__ void bnrelu_inplace(float* __restrict__ x, const float* __restrict__ mean,
                               const float* __restrict__ rstd, int C, int HW, int total) {
    int idx = blockIdx.x * blockDim.x + threadIdx.x;
    if (idx >= total) return;
    int c = (idx / HW) % C;
    float v = (x[idx] - mean[c]) * rstd[c];
    x[idx] = fmaxf(v, 0.f);
}

// ---------------------------------------------------------------------------
// feature transpose + L2 normalize: pool1 (B,96,1225) -> feat (B,1225,96)
// ---------------------------------------------------------------------------
__global__ void feat_norm(const float* __restrict__ pool1, float* __restrict__ feat) {
    int idx = blockIdx.x * blockDim.x + threadIdx.x;
    if (idx >= 128 * 1225) return;
    int b = idx / 1225; int n = idx - b * 1225;
    const float* p = pool1 + (size_t)b * 96 * 1225 + n;
    float ss = 0.f;
#pragma unroll 8
    for (int c = 0; c < 96; c++) { float v = __ldg(p + c * 1225); ss += v * v; }
    float inv = 1.f / fmaxf(sqrtf(ss), 1e-12f);
    float* o = feat + (size_t)idx * 96;
#pragma unroll 8
    for (int c = 0; c < 96; c++) o[c] = __ldg(p + c * 1225) * inv;
}

// ---------------------------------------------------------------------------
// K[b,n,p] = exp((feat_n . proto_p - 1) * 10)
// ---------------------------------------------------------------------------
__global__ void kexp_gemm(const float* __restrict__ feat, const float* __restrict__ protos,
                          float* __restrict__ Km) {
    int b = blockIdx.z;
    int n0 = blockIdx.y * 32;
    int p0 = blockIdx.x * 64;
    __shared__ float Af[32][97];
    __shared__ float Bf[64][97];
    for (int i = threadIdx.x; i < 32 * 96; i += 256) {
        int r = i / 96, k = i % 96;
        Af[r][k] = (n0 + r < 1225) ? feat[((size_t)b * 1225 + n0 + r) * 96 + k] : 0.f;
    }
    for (int i = threadIdx.x; i < 64 * 96; i += 256) {
        int r = i / 96, k = i % 96;
        Bf[r][k] = (p0 + r < 300) ? protos[(p0 + r) * 96 + k] : 0.f;
    }
    __syncthreads();
    int tx = threadIdx.x % 64;
    int ty = threadIdx.x / 64;
    float acc[8] = {0,0,0,0,0,0,0,0};
    for (int k = 0; k < 96; k++) {
        float bv = Bf[tx][k];
#pragma unroll
        for (int i = 0; i < 8; i++) acc[i] += Af[ty * 8 + i][k] * bv;
    }
    int p = p0 + tx;
    if (p < 300) {
#pragma unroll
        for (int i = 0; i < 8; i++) {
            int n = n0 + ty * 8 + i;
            if (n < 1225)
                Km[((size_t)b * 1225 + n) * 300 + p] = expf((acc[i] - 1.f) * 10.f);
        }
    }
}

__global__ void fill_kernel(float* p, float v, int n) {
    int i = blockIdx.x * blockDim.x + threadIdx.x;
    if (i < n) p[i] = v;
}

// v[b,p] = (1/300) / sum_n K[b,n,p] * u[b,n]
__global__ void sink_v(const float* __restrict__ Km, const float* __restrict__ u,
                       float* __restrict__ v) {
    int b = blockIdx.x;
    __shared__ float su[1225];
    for (int i = threadIdx.x; i < 1225; i += blockDim.x) su[i] = u[b * 1225 + i];
    __syncthreads();
    int p = threadIdx.x;
    if (p >= 300) return;
    const float* kp = Km + (size_t)b * 1225 * 300 + p;
    float acc = 0.f;
#pragma unroll 4
    for (int n = 0; n < 1225; n++) acc += __ldg(kp + (size_t)n * 300) * su[n];
    v[b * 300 + p] = (1.f / 300.f) / acc;
}

// u[b,n] = (1/1225) / sum_p K[b,n,p] * v[b,p]
__global__ void sink_u(const float* __restrict__ Km, const float* __restrict__ v,
                       float* __restrict__ u) {
    int b = blockIdx.y;
    __shared__ float sv[300];
    for (int i = threadIdx.x; i < 300; i += blockDim.x) sv[i] = v[b * 300 + i];
    __syncthreads();
    int warp = threadIdx.x / 32, lane = threadIdx.x % 32;
    int n = blockIdx.x * 8 + warp;
    if (n >= 1225) return;
    const float* kp = Km + ((size_t)b * 1225 + n) * 300;
    float acc = 0.f;
    for (int k = lane; k < 300; k += 32) acc += kp[k] * sv[k];
#pragma unroll
    for (int s = 16; s > 0; s >>= 1) acc += __shfl_xor_sync(0xffffffff, acc, s);
    if (lane == 0) u[b * 1225 + n] = (1.f / 1225.f) / acc;
}

// z[b,c,n] = 128 * u[b,n] * sum_p (K[b,n,p]*v[b,p]) * protos[p,c]
__global__ void z_gemm(const float* __restrict__ Km, const float* __restrict__ uu,
                       const float* __restrict__ vv, const float* __restrict__ protos,
                       float* __restrict__ z) {
    int b = blockIdx.y;
    int n0 = blockIdx.x * 32;
    __shared__ float Kt[32][65];
    __shared__ float Pt[64][97];
    int tid = threadIdx.y * 96 + threadIdx.x;
    float acc[16];
#pragma unroll
    for (int i = 0; i < 16; i++) acc[i] = 0.f;

    for (int pc = 0; pc < 5; pc++) {
        int p0 = pc * 64;
        for (int i = tid; i < 32 * 64; i += 192) {
            int r = i / 64, j = i % 64;
            int n = n0 + r, p = p0 + j;
            Kt[r][j] = (n < 1225 && p < 300)
                         ? Km[((size_t)b * 1225 + n) * 300 + p] * __ldg(vv + b * 300 + p)
                         : 0.f;
        }
        for (int i = tid; i < 64 * 96; i += 192) {
            int r = i / 96, k = i % 96;
            Pt[r][k] = (p0 + r < 300) ? protos[(p0 + r) * 96 + k] : 0.f;
        }
        __syncthreads();
        int c = threadIdx.x;
        for (int j = 0; j < 64; j++) {
            float pv = Pt[j][c];
#pragma unroll
            for (int i = 0; i < 16; i++) acc[i] += Kt[threadIdx.y + 2 * i][j] * pv;
        }
        __syncthreads();
    }
    int c = threadIdx.x;
#pragma unroll
    for (int i = 0; i < 16; i++) {
        int n = n0 + threadIdx.y + 2 * i;
        if (n < 1225)
            z[((size_t)b * 96 + c) * 1225 + n] = 128.f * __ldg(uu + b * 1225 + n) * acc[i];
    }
}

// ---------------------------------------------------------------------------
// FC GEMM: out[M,N] = A[M,K] @ Wt[N,K]^T (+bias)
// Tile: 32 rows x 128 cols, block 256 = (32 tx) x (8 ty), 4x4 per thread.
// ---------------------------------------------------------------------------
__global__ void fc_gemm(const float* __restrict__ A, const float* __restrict__ Wt,
                        const float* __restrict__ bias, float* __restrict__ out,
                        int M, int N, int K) {
    int n0 = blockIdx.x * 128, m0 = blockIdx.y * 32;
    __shared__ float As[32][33];
    __shared__ float Ws[128][33];
    int tx = threadIdx.x % 32, ty = threadIdx.x / 32;  // ty 0..7
    float acc[4][4];
#pragma unroll
    for (int i = 0; i < 4; i++)
#pragma unroll
        for (int j = 0; j < 4; j++) acc[i][j] = 0.f;

    for (int k0 = 0; k0 < K; k0 += 32) {
        for (int i = threadIdx.x; i < 32 * 32; i += 256) {
            int r = i / 32, j = i % 32;
            As[r][j] = A[(size_t)(m0 + r) * K + k0 + j];
        }
        for (int i = threadIdx.x; i < 128 * 32; i += 256) {
            int r = i / 32, j = i % 32;
            Ws[r][j] = Wt[(size_t)(n0 + r) * K + k0 + j];
        }
        __syncthreads();
#pragma unroll
        for (int k = 0; k < 32; k++) {
            float a[4], w[4];
#pragma unroll
            for (int i = 0; i < 4; i++) a[i] = As[ty + 8 * i][k];
#pragma unroll
            for (int j = 0; j < 4; j++) w[j] = Ws[tx + 32 * j][k];
#pragma unroll
            for (int i = 0; i < 4; i++)
#pragma unroll
                for (int j = 0; j < 4; j++) acc[i][j] += a[i] * w[j];
        }
        __syncthreads();
    }
#pragma unroll
    for (int j = 0; j < 4; j++) {
        float bv = bias ? bias[n0 + tx + 32 * j] : 0.f;
#pragma unroll
        for (int i = 0; i < 4; i++)
            out[(size_t)(m0 + ty + 8 * i) * N + n0 + tx + 32 * j] = acc[i][j] + bv;
    }
}

// BatchNorm1d (train mode) + ReLU, in-place.  One thread per feature.
__global__ void bn1d_relu(float* __restrict__ x, int M, int N) {
    int f = blockIdx.x * blockDim.x + threadIdx.x;
    if (f >= N) return;
    float s1 = 0.f, s2 = 0.f;
    for (int r = 0; r < M; r++) {
        float v = x[(size_t)r * N + f]; s1 += v; s2 += v * v;
    }
    float m = s1 / M;
    float var = s2 / M - m * m;
    float rs = rsqrtf(var + 1e-5f);
    for (int r = 0; r < M; r++) {
        float v = x[(size_t)r * N + f];
        x[(size_t)r * N + f] = fmaxf((v - m) * rs, 0.f);
    }
}

// Row-wise L2 normalize (128 x 128)
__global__ void l2norm(const float* __restrict__ y, float* __restrict__ out) {
    int m = blockIdx.x, t = threadIdx.x;
    float v = y[m * 128 + t];
    __shared__ float s[128];
    s[t] = v * v;
    __syncthreads();
    for (int st = 64; st > 0; st >>= 1) {
        if (t < st) s[t] += s[t + st];
        __syncthreads();
    }
    out[m * 128 + t] = v * rsqrtf(s[0]);
}

// ---------------------------------------------------------------------------
// Launch
// ---------------------------------------------------------------------------
extern "C" void kernel_launch(void* const* d_in, const int* in_sizes, int n_in,
                              void* d_out, int out_size) {
    const float* x      = (const float*)d_in[0];
    const float* sent_w = (const float*)d_in[1];
    const float* protos = (const float*)d_in[2];
    const float* w1     = (const float*)d_in[3];
    const float* w2     = (const float*)d_in[4];
    const float* w3     = (const float*)d_in[5];
    const float* w4     = (const float*)d_in[6];
    const float* w5     = (const float*)d_in[7];
    const float* w6     = (const float*)d_in[8];
    const float* w7     = (const float*)d_in[9];
    const float* b7     = (const float*)d_in[10];
    float* out = (float*)d_out;

    float *pA, *pP1, *pF, *pK, *pu, *pv, *pB2, *pC3, *pD3, *pE, *pf1, *pf2, *pm, *pr, *pp;
    cudaGetSymbolAddress((void**)&pA,  g_A);
    cudaGetSymbolAddress((void**)&pP1, g_P1);
    cudaGetSymbolAddress((void**)&pF,  g_F);
    cudaGetSymbolAddress((void**)&pK,  g_Km);
    cudaGetSymbolAddress((void**)&pu,  g_u);
    cudaGetSymbolAddress((void**)&pv,  g_v);
    cudaGetSymbolAddress((void**)&pB2, g_B2);
    cudaGetSymbolAddress((void**)&pC3, g_C3);
    cudaGetSymbolAddress((void**)&pD3, g_D3);
    cudaGetSymbolAddress((void**)&pE,  g_E);
    cudaGetSymbolAddress((void**)&pf1, g_fc1);
    cudaGetSymbolAddress((void**)&pf2, g_fc2);
    cudaGetSymbolAddress((void**)&pm,  g_mean);
    cudaGetSymbolAddress((void**)&pr,  g_rstd);
    cudaGetSymbolAddress((void**)&pp,  g_part);

    // sentinel block: conv(2->96, 72x72) + BN + ReLU + pool -> (96,35,35)
    conv3x3<<<dim3(21, 6, 128), 128>>>(x, sent_w, pA, 2, 96, 72, 72);
    bn2d_part<<<dim3(96, BN_SL), 256>>>(pA, pp, 128, 96, 72 * 72);
    bn2d_fin<<<1, 512>>>(pp, pm, pr, 96, 128.f * 5184.f);
    {
        int total = 128 * 96 * 35 * 35;
        bnrelu_pool<<<(total + 255) / 256, 256>>>(pA, pP1, pm, pr, 96, 72, 72, 35, 35, total);
    }

    // prototypes: normalize features, K = exp((S-1)*10)
    feat_norm<<<(128 * 1225 + 255) / 256, 256>>>(pP1, pF);
    kexp_gemm<<<dim3(5, 39, 128), 256>>>(pF, protos, pK);

    // sinkhorn (10 iterations)
    fill_kernel<<<(128 * 1225 + 255) / 256, 256>>>(pu, 1.f, 128 * 1225);
    for (int it = 0; it < 10; it++) {
        sink_v<<<128, 320>>>(pK, pu, pv);
        sink_u<<<dim3(154, 128), 256>>>(pK, pv, pu);
    }
    z_gemm<<<dim3(39, 128), dim3(96, 2)>>>(pK, pu, pv, protos, pP1);

    // encoder block 1: conv 96->192 (35x35) + BN + ReLU + pool -> (192,17,17)
    conv3x3<<<dim3(5, 12, 128), 128>>>(pP1, w1, pA, 96, 192, 35, 35);
    bn2d_part<<<dim3(192, BN_SL), 256>>>(pA, pp, 128, 192, 1225);
    bn2d_fin<<<1, 512>>>(pp, pm, pr, 192, 128.f * 1225.f);
    {
        int total = 128 * 192 * 17 * 17;
        bnrelu_pool<<<(total + 255) / 256, 256>>>(pA, pB2, pm, pr, 192, 35, 35, 17, 17, total);
    }

    // block 2: conv 192->384 (17x17) + BN + ReLU   (289 px -> 160 thr x 2 px)
    conv3x3<<<dim3(1, 24, 128), 160>>>(pB2, w2, pC3, 192, 384, 17, 17);
    bn2d_part<<<dim3(384, BN_SL), 256>>>(pC3, pp, 128, 384, 289);
    bn2d_fin<<<1, 512>>>(pp, pm, pr, 384, 128.f * 289.f);
    {
        int total = 128 * 384 * 289;
        bnrelu_inplace<<<(total + 255) / 256, 256>>>(pC3, pm, pr, 384, 289, total);
    }

    // block 3: conv 384->384 (17x17) + BN + ReLU
    conv3x3<<<dim3(1, 24, 128), 160>>>(pC3, w3, pD3, 384, 384, 17, 17);
    bn2d_part<<<dim3(384, BN_SL), 256>>>(pD3, pp, 128, 384, 289);
    bn2d_fin<<<1, 512>>>(pp, pm, pr, 384, 128.f * 289.f);
    {
        int total = 128 * 384 * 289;
        bnrelu_inplace<<<(total + 255) / 256, 256>>>(pD3, pm, pr, 384, 289, total);
    }

    // block 4: conv 384->192 (17x17) + BN + ReLU + pool -> (192,8,8)
    conv3x3<<<dim3(1, 12, 128), 160>>>(pD3, w4, pA, 384, 192, 17, 17);
    bn2d_part<<<dim3(192, BN_SL), 256>>>(pA, pp, 128, 192, 289);
    bn2d_fin<<<1, 512>>>(pp, pm, pr, 192, 128.f * 289.f);
    {
        int total = 128 * 192 * 8 * 8;
        bnrelu_pool<<<(total + 255) / 256, 256>>>(pA, pE, pm, pr, 192, 17, 17, 8, 8, total);
    }

    // FC head
    fc_gemm<<<dim3(32, 4), 256>>>(pE, w5, nullptr, pf1, 128, 4096, 12288);
    bn1d_relu<<<16, 256>>>(pf1, 128, 4096);
    fc_gemm<<<dim3(32, 4), 256>>>(pf1, w6, nullptr, pf2, 128, 4096, 4096);
    bn1d_relu<<<16, 256>>>(pf2, 128, 4096);
    fc_gemm<<<dim3(1, 4), 256>>>(pf2, w7, b7, pf1, 128, 128, 4096);
    l2norm<<<128, 128>>>(pf1, out);
}

// round 5
// speedup vs baseline: 1.4004x; 1.0474x over previous
#include <cuda_runtime.h>
#include <math.h>

// ---------------------------------------------------------------------------
// Scratch (static device globals -- no allocation anywhere)
// ---------------------------------------------------------------------------
__device__ float g_A [128*96*72*72];        // conv1 out, later w1 out, later w4 out
__device__ float g_P1[128*96*35*35];        // pool1, later z (soft-assigned feats)
__device__ float g_F [128*1225*96];         // normalized features (B,HW,C)
__device__ float g_Km[128*1225*300];        // sinkhorn kernel matrix K
__device__ float g_u [128*1225];
__device__ float g_v [128*300];
__device__ float g_B2[128*192*17*17];       // pool2
__device__ float g_C3[128*384*17*17];       // conv w2 out
__device__ float g_D3[128*384*17*17];       // conv w3 out
__device__ float g_E [128*192*8*8];         // pool4 (flatten input to FC)
__device__ float g_fc1[128*4096];
__device__ float g_fc2[128*4096];
__device__ float g_mean[512];
__device__ float g_rstd[512];
__device__ float g_part[512*16*2];          // BN partial sums

// ---------------------------------------------------------------------------
// f32x2 helpers
// ---------------------------------------------------------------------------
__device__ __forceinline__ unsigned long long pk2(float a, float b) {
    unsigned long long r;
    asm("mov.b64 %0, {%1, %2};" : "=l"(r) : "f"(a), "f"(b));
    return r;
}
__device__ __forceinline__ void fma2(unsigned long long& d, unsigned long long a,
                                     unsigned long long b) {
    asm("fma.rn.f32x2 %0, %1, %2, %3;" : "=l"(d) : "l"(a), "l"(b), "l"(d));
}
__device__ __forceinline__ void unpk2(float& lo, float& hi, unsigned long long v) {
    asm("mov.b64 {%0, %1}, %2;" : "=f"(lo), "=f"(hi) : "l"(v));
}

// ---------------------------------------------------------------------------
// 3x3 conv, stride 1, pad 1 (cross-correlation, NCHW / OIHW).
// Each thread: 4 consecutive pixels of one row (2 f32x2 pairs), CO_T=8 output
// channels. Weights pre-duplicated {w,w} in shared, hoisted per-co via wide
// LDS. Inner loop: 144 FFMA2 per input channel -- FMA-pipe bound.
// WT = ceil(W/4); one thread slot per (row, 4-col group).
// ---------------------------------------------------------------------------
#define CI_CHUNK 32
#define CO_T 8

__global__ void conv3x3(const float* __restrict__ in, const float* __restrict__ wt,
                        float* __restrict__ out, int Cin, int Cout, int H, int W,
                        int WT) {
    const int HW = H * W;
    const int n   = blockIdx.z;
    const int co0 = blockIdx.y * CO_T;
    int g = blockIdx.x * blockDim.x + threadIdx.x;
    int r  = g / WT;
    int c0 = (g - r * WT) * 4;
    const bool active = r < H;
    if (!active) { r = 0; c0 = 0; }

    // validity of the 3 rows (r-1..r+1) and 6 cols (c0-1..c0+4)
    bool rv0 = (r - 1 >= 0), rv2 = (r + 1 < H);
    bool cv[6];
#pragma unroll
    for (int j = 0; j < 6; j++) {
        int cc_ = c0 - 1 + j;
        cv[j] = active && cc_ >= 0 && cc_ < W;
    }
    bool pv[3][6];
#pragma unroll
    for (int j = 0; j < 6; j++) {
        pv[0][j] = rv0 && cv[j];
        pv[1][j] = cv[j];
        pv[2][j] = rv2 && cv[j];
    }

    unsigned long long accA[CO_T], accB[CO_T];
#pragma unroll
    for (int i = 0; i < CO_T; i++) { accA[i] = 0ull; accB[i] = 0ull; }

    // duplicated weight pairs [ci][co][k], k padded 9->10 (80B rows, 16B aligned)
    __shared__ __align__(16) float2 sw[CI_CHUNK][CO_T][10];

    const float* base = in + (size_t)n * Cin * HW + (r - 1) * W + (c0 - 1);

    for (int cb = 0; cb < Cin; cb += CI_CHUNK) {
        int cc = min(CI_CHUNK, Cin - cb);
        int tot = cc * CO_T * 9;
        for (int i = threadIdx.x; i < tot; i += blockDim.x) {
            int k = i % 9; int t = i / 9; int co = t % CO_T; int ci = t / CO_T;
            float wv = wt[((size_t)(co0 + co) * Cin + (cb + ci)) * 9 + k];
            sw[ci][co][k] = make_float2(wv, wv);
        }
        __syncthreads();

        for (int ci = 0; ci < cc; ci++) {
            const float* p = base + (size_t)(cb + ci) * HW;
            float t[3][6];
#pragma unroll
            for (int dy = 0; dy < 3; dy++)
#pragma unroll
                for (int j = 0; j < 6; j++)
                    t[dy][j] = pv[dy][j] ? __ldg(p + dy * W + j) : 0.f;

            // tap pairs P[dy][k] = {t[dy][k], t[dy][k+1]}, k=0..4
            // pixel-pair A (cols c0,c0+1) uses P[dy][dx]; pair B uses P[dy][dx+2]
            unsigned long long P[3][5];
#pragma unroll
            for (int dy = 0; dy < 3; dy++)
#pragma unroll
                for (int k = 0; k < 5; k++)
                    P[dy][k] = pk2(t[dy][k], t[dy][k + 1]);

#pragma unroll
            for (int co = 0; co < CO_T; co++) {
                const float2* wrow = sw[ci][co];
                ulonglong2 wab = *reinterpret_cast<const ulonglong2*>(wrow);
                ulonglong2 wcd = *reinterpret_cast<const ulonglong2*>(wrow + 2);
                ulonglong2 wef = *reinterpret_cast<const ulonglong2*>(wrow + 4);
                ulonglong2 wgh = *reinterpret_cast<const ulonglong2*>(wrow + 6);
                unsigned long long w8 =
                    *reinterpret_cast<const unsigned long long*>(wrow + 8);
                fma2(accA[co], P[0][0], wab.x); fma2(accB[co], P[0][2], wab.x);
                fma2(accA[co], P[0][1], wab.y); fma2(accB[co], P[0][3], wab.y);
                fma2(accA[co], P[0][2], wcd.x); fma2(accB[co], P[0][4], wcd.x);
                fma2(accA[co], P[1][0], wcd.y); fma2(accB[co], P[1][2], wcd.y);
                fma2(accA[co], P[1][1], wef.x); fma2(accB[co], P[1][3], wef.x);
                fma2(accA[co], P[1][2], wef.y); fma2(accB[co], P[1][4], wef.y);
                fma2(accA[co], P[2][0], wgh.x); fma2(accB[co], P[2][2], wgh.x);
                fma2(accA[co], P[2][1], wgh.y); fma2(accB[co], P[2][3], wgh.y);
                fma2(accA[co], P[2][2], w8);    fma2(accB[co], P[2][4], w8);
            }
        }
        __syncthreads();
    }

    if (active) {
        bool v1 = c0 + 1 < W, v2 = c0 + 2 < W, v3 = c0 + 3 < W;
#pragma unroll
        for (int co = 0; co < CO_T; co++) {
            float o0, o1, o2, o3;
            unpk2(o0, o1, accA[co]);
            unpk2(o2, o3, accB[co]);
            float* op = out + ((size_t)n * Cout + co0 + co) * HW + r * W + c0;
            op[0] = o0;
            if (v1) op[1] = o1;
            if (v2) op[2] = o2;
            if (v3) op[3] = o3;
        }
    }
}

// ---------------------------------------------------------------------------
// BatchNorm2d stats, two-stage.
// ---------------------------------------------------------------------------
#define BN_SL 16
__global__ void bn2d_part(const float* __restrict__ x, float* __restrict__ part,
                          int N, int C, int HW) {
    int c = blockIdx.x, sl = blockIdx.y;
    int nper = N / BN_SL;
    float s1 = 0.f, s2 = 0.f;
    for (int n = sl * nper; n < (sl + 1) * nper; n++) {
        const float* p = x + ((size_t)n * C + c) * HW;
        for (int j = threadIdx.x; j < HW; j += blockDim.x) {
            float v = p[j]; s1 += v; s2 += v * v;
        }
    }
    __shared__ float r1[256], r2[256];
    r1[threadIdx.x] = s1; r2[threadIdx.x] = s2;
    __syncthreads();
    for (int s = 128; s > 0; s >>= 1) {
        if (threadIdx.x < s) { r1[threadIdx.x] += r1[threadIdx.x + s];
                               r2[threadIdx.x] += r2[threadIdx.x + s]; }
        __syncthreads();
    }
    if (threadIdx.x == 0) {
        part[(c * BN_SL + sl) * 2 + 0] = r1[0];
        part[(c * BN_SL + sl) * 2 + 1] = r2[0];
    }
}

__global__ void bn2d_fin(const float* __restrict__ part, float* __restrict__ mean,
                         float* __restrict__ rstd, int C, float count) {
    int c = blockIdx.x * blockDim.x + threadIdx.x;
    if (c >= C) return;
    float s1 = 0.f, s2 = 0.f;
#pragma unroll
    for (int j = 0; j < BN_SL; j++) {
        s1 += part[(c * BN_SL + j) * 2 + 0];
        s2 += part[(c * BN_SL + j) * 2 + 1];
    }
    float m = s1 / count;
    float var = s2 / count - m * m;
    mean[c] = m;
    rstd[c] = rsqrtf(var + 1e-5f);
}

// maxpool(3,2,VALID) on raw conv output, then BN + ReLU (commutes with pool)
__global__ void bnrelu_pool(const float* __restrict__ in, float* __restrict__ out,
                            const float* __restrict__ mean, const float* __restrict__ rstd,
                            int C, int H, int W, int Ho, int Wo, int total) {
    int idx = blockIdx.x * blockDim.x + threadIdx.x;
    if (idx >= total) return;
    int wo = idx % Wo; int t = idx / Wo;
    int ho = t % Ho; t /= Ho;
    int c = t % C; int n = t / C;
    const float* p = in + (((size_t)n * C + c) * H + 2 * ho) * W + 2 * wo;
    float m = -INFINITY;
#pragma unroll
    for (int r = 0; r < 3; r++)
#pragma unroll
        for (int q = 0; q < 3; q++) m = fmaxf(m, p[r * W + q]);
    float v = (m - mean[c]) * rstd[c];
    out[idx] = fmaxf(v, 0.f);
}

__global__ void bnrelu_inplace(float* __restrict__ x, const float* __restrict__ mean,
                               const float* __restrict__ rstd, int C, int HW, int total) {
    int idx = blockIdx.x * blockDim.x + threadIdx.x;
    if (idx >= total) return;
    int c = (idx / HW) % C;
    float v = (x[idx] - mean[c]) * rstd[c];
    x[idx] = fmaxf(v, 0.f);
}

// ---------------------------------------------------------------------------
// feature transpose + L2 normalize: pool1 (B,96,1225) -> feat (B,1225,96)
// ---------------------------------------------------------------------------
__global__ void feat_norm(const float* __restrict__ pool1, float* __restrict__ feat) {
    int idx = blockIdx.x * blockDim.x + threadIdx.x;
    if (idx >= 128 * 1225) return;
    int b = idx / 1225; int n = idx - b * 1225;
    const float* p = pool1 + (size_t)b * 96 * 1225 + n;
    float ss = 0.f;
#pragma unroll 8
    for (int c = 0; c < 96; c++) { float v = __ldg(p + c * 1225); ss += v * v; }
    float inv = 1.f / fmaxf(sqrtf(ss), 1e-12f);
    float* o = feat + (size_t)idx * 96;
#pragma unroll 8
    for (int c = 0; c < 96; c++) o[c] = __ldg(p + c * 1225) * inv;
}

// ---------------------------------------------------------------------------
// K[b,n,p] = exp((feat_n . proto_p - 1) * 10)
// ---------------------------------------------------------------------------
__global__ void kexp_gemm(const float* __restrict__ feat, const float* __restrict__ protos,
                          float* __restrict__ Km) {
    int b = blockIdx.z;
    int n0 = blockIdx.y * 32;
    int p0 = blockIdx.x * 64;
    __shared__ float Af[32][97];
    __shared__ float Bf[64][97];
    for (int i = threadIdx.x; i < 32 * 96; i += 256) {
        int r = i / 96, k = i % 96;
        Af[r][k] = (n0 + r < 1225) ? feat[((size_t)b * 1225 + n0 + r) * 96 + k] : 0.f;
    }
    for (int i = threadIdx.x; i < 64 * 96; i += 256) {
        int r = i / 96, k = i % 96;
        Bf[r][k] = (p0 + r < 300) ? protos[(p0 + r) * 96 + k] : 0.f;
    }
    __syncthreads();
    int tx = threadIdx.x % 64;
    int ty = threadIdx.x / 64;
    float acc[8] = {0,0,0,0,0,0,0,0};
    for (int k = 0; k < 96; k++) {
        float bv = Bf[tx][k];
#pragma unroll
        for (int i = 0; i < 8; i++) acc[i] += Af[ty * 8 + i][k] * bv;
    }
    int p = p0 + tx;
    if (p < 300) {
#pragma unroll
        for (int i = 0; i < 8; i++) {
            int n = n0 + ty * 8 + i;
            if (n < 1225)
                Km[((size_t)b * 1225 + n) * 300 + p] = expf((acc[i] - 1.f) * 10.f);
        }
    }
}

__global__ void fill_kernel(float* p, float v, int n) {
    int i = blockIdx.x * blockDim.x + threadIdx.x;
    if (i < n) p[i] = v;
}

// v[b,p] = (1/300) / sum_n K[b,n,p] * u[b,n]
__global__ void sink_v(const float* __restrict__ Km, const float* __restrict__ u,
                       float* __restrict__ v) {
    int b = blockIdx.x;
    __shared__ float su[1225];
    for (int i = threadIdx.x; i < 1225; i += blockDim.x) su[i] = u[b * 1225 + i];
    __syncthreads();
    int p = threadIdx.x;
    if (p >= 300) return;
    const float* kp = Km + (size_t)b * 1225 * 300 + p;
    float acc = 0.f;
#pragma unroll 4
    for (int n = 0; n < 1225; n++) acc += __ldg(kp + (size_t)n * 300) * su[n];
    v[b * 300 + p] = (1.f / 300.f) / acc;
}

// u[b,n] = (1/1225) / sum_p K[b,n,p] * v[b,p]
__global__ void sink_u(const float* __restrict__ Km, const float* __restrict__ v,
                       float* __restrict__ u) {
    int b = blockIdx.y;
    __shared__ float sv[300];
    for (int i = threadIdx.x; i < 300; i += blockDim.x) sv[i] = v[b * 300 + i];
    __syncthreads();
    int warp = threadIdx.x / 32, lane = threadIdx.x % 32;
    int n = blockIdx.x * 8 + warp;
    if (n >= 1225) return;
    const float* kp = Km + ((size_t)b * 1225 + n) * 300;
    float acc = 0.f;
    for (int k = lane; k < 300; k += 32) acc += kp[k] * sv[k];
#pragma unroll
    for (int s = 16; s > 0; s >>= 1) acc += __shfl_xor_sync(0xffffffff, acc, s);
    if (lane == 0) u[b * 1225 + n] = (1.f / 1225.f) / acc;
}

// z[b,c,n] = 128 * u[b,n] * sum_p (K[b,n,p]*v[b,p]) * protos[p,c]
__global__ void z_gemm(const float* __restrict__ Km, const float* __restrict__ uu,
                       const float* __restrict__ vv, const float* __restrict__ protos,
                       float* __restrict__ z) {
    int b = blockIdx.y;
    int n0 = blockIdx.x * 32;
    __shared__ float Kt[32][65];
    __shared__ float Pt[64][97];
    int tid = threadIdx.y * 96 + threadIdx.x;
    float acc[16];
#pragma unroll
    for (int i = 0; i < 16; i++) acc[i] = 0.f;

    for (int pc = 0; pc < 5; pc++) {
        int p0 = pc * 64;
        for (int i = tid; i < 32 * 64; i += 192) {
            int r = i / 64, j = i % 64;
            int n = n0 + r, p = p0 + j;
            Kt[r][j] = (n < 1225 && p < 300)
                         ? Km[((size_t)b * 1225 + n) * 300 + p] * __ldg(vv + b * 300 + p)
                         : 0.f;
        }
        for (int i = tid; i < 64 * 96; i += 192) {
            int r = i / 96, k = i % 96;
            Pt[r][k] = (p0 + r < 300) ? protos[(p0 + r) * 96 + k] : 0.f;
        }
        __syncthreads();
        int c = threadIdx.x;
        for (int j = 0; j < 64; j++) {
            float pv = Pt[j][c];
#pragma unroll
            for (int i = 0; i < 16; i++) acc[i] += Kt[threadIdx.y + 2 * i][j] * pv;
        }
        __syncthreads();
    }
    int c = threadIdx.x;
#pragma unroll
    for (int i = 0; i < 16; i++) {
        int n = n0 + threadIdx.y + 2 * i;
        if (n < 1225)
            z[((size_t)b * 96 + c) * 1225 + n] = 128.f * __ldg(uu + b * 1225 + n) * acc[i];
    }
}

// ---------------------------------------------------------------------------
// FC GEMM: out[M,N] = A[M,K] @ Wt[N,K]^T (+bias)
// Tile: 32 rows x 128 cols, block 256 = (32 tx) x (8 ty), 4x4 per thread.
// ---------------------------------------------------------------------------
__global__ void fc_gemm(const float* __restrict__ A, const float* __restrict__ Wt,
                        const float* __restrict__ bias, float* __restrict__ out,
                        int M, int N, int K) {
    int n0 = blockIdx.x * 128, m0 = blockIdx.y * 32;
    __shared__ float As[32][33];
    __shared__ float Ws[128][33];
    int tx = threadIdx.x % 32, ty = threadIdx.x / 32;  // ty 0..7
    float acc[4][4];
#pragma unroll
    for (int i = 0; i < 4; i++)
#pragma unroll
        for (int j = 0; j < 4; j++) acc[i][j] = 0.f;

    for (int k0 = 0; k0 < K; k0 += 32) {
        for (int i = threadIdx.x; i < 32 * 32; i += 256) {
            int r = i / 32, j = i % 32;
            As[r][j] = A[(size_t)(m0 + r) * K + k0 + j];
        }
        for (int i = threadIdx.x; i < 128 * 32; i += 256) {
            int r = i / 32, j = i % 32;
            Ws[r][j] = Wt[(size_t)(n0 + r) * K + k0 + j];
        }
        __syncthreads();
#pragma unroll
        for (int k = 0; k < 32; k++) {
            float a[4], w[4];
#pragma unroll
            for (int i = 0; i < 4; i++) a[i] = As[ty + 8 * i][k];
#pragma unroll
            for (int j = 0; j < 4; j++) w[j] = Ws[tx + 32 * j][k];
#pragma unroll
            for (int i = 0; i < 4; i++)
#pragma unroll
                for (int j = 0; j < 4; j++) acc[i][j] += a[i] * w[j];
        }
        __syncthreads();
    }
#pragma unroll
    for (int j = 0; j < 4; j++) {
        float bv = bias ? bias[n0 + tx + 32 * j] : 0.f;
#pragma unroll
        for (int i = 0; i < 4; i++)
            out[(size_t)(m0 + ty + 8 * i) * N + n0 + tx + 32 * j] = acc[i][j] + bv;
    }
}

// BatchNorm1d (train mode) + ReLU, in-place.  One thread per feature.
__global__ void bn1d_relu(float* __restrict__ x, int M, int N) {
    int f = blockIdx.x * blockDim.x + threadIdx.x;
    if (f >= N) return;
    float s1 = 0.f, s2 = 0.f;
    for (int r = 0; r < M; r++) {
        float v = x[(size_t)r * N + f]; s1 += v; s2 += v * v;
    }
    float m = s1 / M;
    float var = s2 / M - m * m;
    float rs = rsqrtf(var + 1e-5f);
    for (int r = 0; r < M; r++) {
        float v = x[(size_t)r * N + f];
        x[(size_t)r * N + f] = fmaxf((v - m) * rs, 0.f);
    }
}

// Row-wise L2 normalize (128 x 128)
__global__ void l2norm(const float* __restrict__ y, float* __restrict__ out) {
    int m = blockIdx.x, t = threadIdx.x;
    float v = y[m * 128 + t];
    __shared__ float s[128];
    s[t] = v * v;
    __syncthreads();
    for (int st = 64; st > 0; st >>= 1) {
        if (t < st) s[t] += s[t + st];
        __syncthreads();
    }
    out[m * 128 + t] = v * rsqrtf(s[0]);
}

// ---------------------------------------------------------------------------
// Launch
// ---------------------------------------------------------------------------
extern "C" void kernel_launch(void* const* d_in, const int* in_sizes, int n_in,
                              void* d_out, int out_size) {
    const float* x      = (const float*)d_in[0];
    const float* sent_w = (const float*)d_in[1];
    const float* protos = (const float*)d_in[2];
    const float* w1     = (const float*)d_in[3];
    const float* w2     = (const float*)d_in[4];
    const float* w3     = (const float*)d_in[5];
    const float* w4     = (const float*)d_in[6];
    const float* w5     = (const float*)d_in[7];
    const float* w6     = (const float*)d_in[8];
    const float* w7     = (const float*)d_in[9];
    const float* b7     = (const float*)d_in[10];
    float* out = (float*)d_out;

    float *pA, *pP1, *pF, *pK, *pu, *pv, *pB2, *pC3, *pD3, *pE, *pf1, *pf2, *pm, *pr, *pp;
    cudaGetSymbolAddress((void**)&pA,  g_A);
    cudaGetSymbolAddress((void**)&pP1, g_P1);
    cudaGetSymbolAddress((void**)&pF,  g_F);
    cudaGetSymbolAddress((void**)&pK,  g_Km);
    cudaGetSymbolAddress((void**)&pu,  g_u);
    cudaGetSymbolAddress((void**)&pv,  g_v);
    cudaGetSymbolAddress((void**)&pB2, g_B2);
    cudaGetSymbolAddress((void**)&pC3, g_C3);
    cudaGetSymbolAddress((void**)&pD3, g_D3);
    cudaGetSymbolAddress((void**)&pE,  g_E);
    cudaGetSymbolAddress((void**)&pf1, g_fc1);
    cudaGetSymbolAddress((void**)&pf2, g_fc2);
    cudaGetSymbolAddress((void**)&pm,  g_mean);
    cudaGetSymbolAddress((void**)&pr,  g_rstd);
    cudaGetSymbolAddress((void**)&pp,  g_part);

    // sentinel block: conv(2->96, 72x72) + BN + ReLU + pool -> (96,35,35)
    // WT=18, 72*18=1296 thread slots -> 6 x 256
    conv3x3<<<dim3(6, 12, 128), 256>>>(x, sent_w, pA, 2, 96, 72, 72, 18);
    bn2d_part<<<dim3(96, BN_SL), 256>>>(pA, pp, 128, 96, 72 * 72);
    bn2d_fin<<<1, 512>>>(pp, pm, pr, 96, 128.f * 5184.f);
    {
        int total = 128 * 96 * 35 * 35;
        bnrelu_pool<<<(total + 255) / 256, 256>>>(pA, pP1, pm, pr, 96, 72, 72, 35, 35, total);
    }

    // prototypes: normalize features, K = exp((S-1)*10)
    feat_norm<<<(128 * 1225 + 255) / 256, 256>>>(pP1, pF);
    kexp_gemm<<<dim3(5, 39, 128), 256>>>(pF, protos, pK);

    // sinkhorn (10 iterations)
    fill_kernel<<<(128 * 1225 + 255) / 256, 256>>>(pu, 1.f, 128 * 1225);
    for (int it = 0; it < 10; it++) {
        sink_v<<<128, 320>>>(pK, pu, pv);
        sink_u<<<dim3(154, 128), 256>>>(pK, pv, pu);
    }
    z_gemm<<<dim3(39, 128), dim3(96, 2)>>>(pK, pu, pv, protos, pP1);

    // encoder block 1: conv 96->192 (35x35): WT=9, 35*9=315 slots -> 1 x 320
    conv3x3<<<dim3(1, 24, 128), 320>>>(pP1, w1, pA, 96, 192, 35, 35, 9);
    bn2d_part<<<dim3(192, BN_SL), 256>>>(pA, pp, 128, 192, 1225);
    bn2d_fin<<<1, 512>>>(pp, pm, pr, 192, 128.f * 1225.f);
    {
        int total = 128 * 192 * 17 * 17;
        bnrelu_pool<<<(total + 255) / 256, 256>>>(pA, pB2, pm, pr, 192, 35, 35, 17, 17, total);
    }

    // block 2: conv 192->384 (17x17): WT=5, 17*5=85 slots -> 1 x 96
    conv3x3<<<dim3(1, 48, 128), 96>>>(pB2, w2, pC3, 192, 384, 17, 17, 5);
    bn2d_part<<<dim3(384, BN_SL), 256>>>(pC3, pp, 128, 384, 289);
    bn2d_fin<<<1, 512>>>(pp, pm, pr, 384, 128.f * 289.f);
    {
        int total = 128 * 384 * 289;
        bnrelu_inplace<<<(total + 255) / 256, 256>>>(pC3, pm, pr, 384, 289, total);
    }

    // block 3: conv 384->384 (17x17)
    conv3x3<<<dim3(1, 48, 128), 96>>>(pC3, w3, pD3, 384, 384, 17, 17, 5);
    bn2d_part<<<dim3(384, BN_SL), 256>>>(pD3, pp, 128, 384, 289);
    bn2d_fin<<<1, 512>>>(pp, pm, pr, 384, 128.f * 289.f);
    {
        int total = 128 * 384 * 289;
        bnrelu_inplace<<<(total + 255) / 256, 256>>>(pD3, pm, pr, 384, 289, total);
    }

    // block 4: conv 384->192 (17x17) + BN + ReLU + pool -> (192,8,8)
    conv3x3<<<dim3(1, 24, 128), 96>>>(pD3, w4, pA, 384, 192, 17, 17, 5);
    bn2d_part<<<dim3(192, BN_SL), 256>>>(pA, pp, 128, 192, 289);
    bn2d_fin<<<1, 512>>>(pp, pm, pr, 192, 128.f * 289.f);
    {
        int total = 128 * 192 * 8 * 8;
        bnrelu_pool<<<(total + 255) / 256, 256>>>(pA, pE, pm, pr, 192, 17, 17, 8, 8, total);
    }

    // FC head
    fc_gemm<<<dim3(32, 4), 256>>>(pE, w5, nullptr, pf1, 128, 4096, 12288);
    bn1d_relu<<<16, 256>>>(pf1, 128, 4096);
    fc_gemm<<<dim3(32, 4), 256>>>(pf1, w6, nullptr, pf2, 128, 4096, 4096);
    bn1d_relu<<<16, 256>>>(pf2, 128, 4096);
    fc_gemm<<<dim3(1, 4), 256>>>(pf2, w7, b7, pf1, 128, 128, 4096);
    l2norm<<<128, 128>>>(pf1, out);
}